// round 15
// baseline (speedup 1.0000x reference)
#include <cuda_runtime.h>
#include <cuda_fp16.h>
#include <cstdint>

// Problem constants
#define BATCH   32768
#define TSTEPS  30
#define HID     384
// K layout: cols 0..7 rowvec, 8..15 zero, 16..399 hidden  (kb0 = pure rowvec block)
#define NKB     25      // K blocks of 16
#define NMAIN   144     // fragments per kb (24 ub * 6: gate3 x uh2)
#define MROWS   64      // batch rows per CTA
#define NTH     512     // 16 warps = 2 M-halves x 8 col-warps; 1 CTA/SM
#define LDHH    408     // sA row stride in halfs
#define WLDH    204     // row stride in 32-bit words
#define AHSZ    (MROWS*LDHH)
#define DECLD   66      // sDec row stride in halfs

// -------- static device scratch (fp16 fragment tables) --------
__device__ uint2 g_Bh[NKB * NMAIN * 32];    // main GEMM B (r,z,n_h)
__device__ uint2 g_Bnih[48 * 32];           // n_i B: kb=0 only, 48 usb
__device__ uint2 g_Wd1h[24 * 8 * 32];       // decode B (kd = main kb-1)

__device__ __forceinline__ unsigned packh2(float a, float b) {
    __half2 h = __floats2half2_rn(a, b);
    return *reinterpret_cast<unsigned*>(&h);
}
__device__ __forceinline__ float tanh_hw(float x) {
    float y; asm("tanh.approx.f32 %0, %1;" : "=f"(y) : "f"(x)); return y;
}
__device__ __forceinline__ float sigf(float x) {
    return fmaf(0.5f, tanh_hw(0.5f * x), 0.5f);
}

__device__ __forceinline__ void mma_f16(float* c, const unsigned* a, unsigned b0, unsigned b1) {
    asm volatile(
        "mma.sync.aligned.m16n8k16.row.col.f32.f16.f16.f32 "
        "{%0,%1,%2,%3}, {%4,%5,%6,%7}, {%8,%9}, {%0,%1,%2,%3};\n"
        : "+f"(c[0]), "+f"(c[1]), "+f"(c[2]), "+f"(c[3])
        : "r"(a[0]), "r"(a[1]), "r"(a[2]), "r"(a[3]), "r"(b0), "r"(b1));
}

// -------- prep value helpers (identical to round 14) --------
__device__ float bval_main(int k, int ub, int colub,
                           const float* Wih, const float* bih,
                           const float* Whh, const float* bhh,
                           const float* Wp, const float* bp,
                           const float* Ws, const float* bs) {
    int gate = colub >> 4;                   // 0=r,1=z,2=n_h
    int u = ub * 16 + (colub & 15);
    if (k >= 16) {
        int grow = (gate == 2 ? 768 : gate * 384) + u;
        return Whh[grow * HID + (k - 16)];
    }
    if (gate == 2) return (k == 0) ? bhh[768 + u] : 0.0f;   // n_h: bias only
    if (k >= 8) return 0.0f;
    int grow = gate * 384 + u;
    const float* wr = Wih + grow * 128;
    float s = 0.0f;
    if (k == 0) {
        s = bih[grow] + bhh[grow];
        for (int m = 0; m < 128; m++) s += bs[m] * wr[m];
    } else if (k == 1) {
        for (int m = 0; m < 128; m++) s += bp[m] * wr[m];
    } else if (k < 5) {
        int d = k - 2;
        for (int m = 0; m < 128; m++) s += Ws[m * 3 + d] * wr[m];
    } else {
        int d = k - 5;
        for (int m = 0; m < 128; m++) s += Wp[m * 3 + d] * wr[m];
    }
    return s;
}

__device__ float bval_ni(int k, int u,
                         const float* Wih, const float* bih,
                         const float* Wp, const float* bp,
                         const float* Ws, const float* bs) {
    if (k >= 8) return 0.0f;                 // n_i: rowvec only
    int grow = 768 + u;
    const float* wr = Wih + grow * 128;
    float s = 0.0f;
    if (k == 0) {
        s = bih[grow];
        for (int m = 0; m < 128; m++) s += bs[m] * wr[m];
    } else if (k == 1) {
        for (int m = 0; m < 128; m++) s += bp[m] * wr[m];
    } else if (k < 5) {
        int d = k - 2;
        for (int m = 0; m < 128; m++) s += Ws[m * 3 + d] * wr[m];
    } else {
        int d = k - 5;
        for (int m = 0; m < 128; m++) s += Wp[m * 3 + d] * wr[m];
    }
    return s;
}

__global__ void prep_kernel(const float* __restrict__ W_ih, const float* __restrict__ b_ih,
                            const float* __restrict__ W_hh, const float* __restrict__ b_hh,
                            const float* __restrict__ Wp,  const float* __restrict__ bp,
                            const float* __restrict__ Ws,  const float* __restrict__ bs,
                            const float* __restrict__ Wd1) {
    int gid = blockIdx.x * blockDim.x + threadIdx.x;
    const int nMain = NKB * NMAIN;
    const int total = (nMain + 48 + 24 * 8) * 32;
    for (int w = gid; w < total; w += gridDim.x * blockDim.x) {
        int fid = w >> 5, lane = w & 31;
        int tig = lane & 3, g = lane >> 2;
        if (fid < nMain) {
            int kb = fid / NMAIN, rem = fid - kb * NMAIN;
            int ub = rem / 6, n8l = rem - ub * 6;
            int colub = n8l * 8 + g;
            int k0 = kb * 16;
            float v00 = bval_main(k0 + 2 * tig,     ub, colub, W_ih, b_ih, W_hh, b_hh, Wp, bp, Ws, bs);
            float v01 = bval_main(k0 + 2 * tig + 1, ub, colub, W_ih, b_ih, W_hh, b_hh, Wp, bp, Ws, bs);
            float v10 = bval_main(k0 + 2 * tig + 8, ub, colub, W_ih, b_ih, W_hh, b_hh, Wp, bp, Ws, bs);
            float v11 = bval_main(k0 + 2 * tig + 9, ub, colub, W_ih, b_ih, W_hh, b_hh, Wp, bp, Ws, bs);
            g_Bh[fid * 32 + lane] = make_uint2(packh2(v00, v01), packh2(v10, v11));
        } else if (fid < nMain + 48) {
            int usb = fid - nMain;
            int u = usb * 8 + g;
            float v00 = bval_ni(2 * tig,     u, W_ih, b_ih, Wp, bp, Ws, bs);
            float v01 = bval_ni(2 * tig + 1, u, W_ih, b_ih, Wp, bp, Ws, bs);
            g_Bnih[usb * 32 + lane] = make_uint2(packh2(v00, v01), packh2(0.0f, 0.0f));
        } else {
            int f = fid - nMain - 48;        // 24 kd * 8 c8 ; kd = main kb-1
            int kd = f >> 3, c8 = f & 7;
            int n = c8 * 8 + g;
            int k = kd * 16 + 2 * tig;
            float v00 = Wd1[n * HID + k];
            float v01 = Wd1[n * HID + k + 1];
            float v10 = Wd1[n * HID + k + 8];
            float v11 = Wd1[n * HID + k + 9];
            g_Wd1h[f * 32 + lane] = make_uint2(packh2(v00, v01), packh2(v10, v11));
        }
    }
}

// -------- main fused GRU rollout: fp16 MMA, M-split warps, 1 CTA/SM --------
__global__ __launch_bounds__(NTH, 1)
void gru_kernel(const float* __restrict__ init_hidden,
                const float* __restrict__ plan,
                const float* __restrict__ gate,
                const float* __restrict__ init_state,
                const float* __restrict__ bd1,
                const float* __restrict__ Wd2,
                const float* __restrict__ bd2,
                float* __restrict__ out) {
    extern __shared__ char smraw[];
    __half* sA0h  = (__half*)smraw;                 // [64][408] ping
    __half* sA1h  = sA0h + AHSZ;                    // pong
    __half* sDech = sA1h + AHSZ;                    // [64][66]
    float*  sbd1  = (float*)(sDech + 64 * DECLD);   // [64]
    float*  sWd2  = sbd1 + 64;                      // [192]
    float*  sbd2  = sWd2 + 192;                     // [4]

    const int tid  = threadIdx.x;
    const int warp = tid >> 5;
    const int lane = tid & 31;
    const int g8   = lane >> 2;
    const int tig  = lane & 3;
    const int wsub = warp & 7;          // column-warp
    const int mh   = warp >> 3;         // M half: rows mh*32 .. mh*32+31
    const int row0 = blockIdx.x * MROWS;

    float st0 = 0.0f, st1 = 0.0f, st2 = 0.0f, gx = 0.0f;   // state lanes (tid<64)

    // ---- init ----
    for (int i = tid; i < MROWS * HID; i += NTH) {
        int r = i / HID, u = i - r * HID;
        sA0h[r * LDHH + 16 + u] = __float2half_rn(init_hidden[(size_t)row0 * HID + i]);
    }
    for (int i = tid; i < MROWS * 8; i += NTH) {   // zero cols 8..15, both buffers
        int r = i >> 3, c = i & 7;
        sA0h[r * LDHH + 8 + c] = __ushort_as_half(0);
        sA1h[r * LDHH + 8 + c] = __ushort_as_half(0);
    }
    if (tid < 64) {
        gx  = gate[row0 + tid];
        st0 = init_state[(size_t)(row0 + tid) * 3 + 0];
        st1 = init_state[(size_t)(row0 + tid) * 3 + 1];
        st2 = init_state[(size_t)(row0 + tid) * 3 + 2];
        const float* pp = plan + (size_t)(row0 + tid) * TSTEPS * 3;   // t=0
        unsigned w0 = packh2(1.0f, gx);
        ((unsigned*)sA0h)[tid * WLDH + 0] = w0;
        ((unsigned*)sA1h)[tid * WLDH + 0] = w0;
        ((unsigned*)sA0h)[tid * WLDH + 1] = packh2(st0, st1);
        ((unsigned*)sA0h)[tid * WLDH + 2] = packh2(st2, gx * pp[0]);
        ((unsigned*)sA0h)[tid * WLDH + 3] = packh2(gx * pp[1], gx * pp[2]);
        sbd1[tid] = bd1[tid];
    }
    if (tid < 192) sWd2[tid] = Wd2[tid];
    if (tid < 3)   sbd2[tid] = bd2[tid];
    __syncthreads();

    // A-fragment loader: this warp's M-half only (mf=2 -> 8 LDS.32)
    auto load_afrag = [&](unsigned* a, const unsigned* Aw, int kb) {
        #pragma unroll
        for (int mf = 0; mf < 2; mf++) {
            int r0 = mh * 32 + mf * 16 + g8;
            int wb = kb * 8 + tig;
            a[mf * 4 + 0] = Aw[r0 * WLDH + wb];
            a[mf * 4 + 1] = Aw[(r0 + 8) * WLDH + wb];
            a[mf * 4 + 2] = Aw[r0 * WLDH + wb + 4];
            a[mf * 4 + 3] = Aw[(r0 + 8) * WLDH + wb + 4];
        }
    };
    // GRU epilogue for one ub (16 cols), acc layout f = gate*2 + uh
    auto gru_epilogue = [&](int ub, const float* acc, const float* accN,
                            const unsigned* Aw, unsigned* AnxtW) {
        #pragma unroll
        for (int mf = 0; mf < 2; mf++)
        #pragma unroll
        for (int uh = 0; uh < 2; uh++)
        #pragma unroll
        for (int h = 0; h < 2; h++) {
            int row = mh * 32 + mf * 16 + g8 + h * 8;
            int widx = row * WLDH + 8 + ub * 8 + uh * 4 + tig;
            __half2 hold2 = *(const __half2*)&Aw[widx];
            float2 holdf = __half22float2(hold2);
            float hn[2];
            #pragma unroll
            for (int q = 0; q < 2; q++) {
                int e = 2 * h + q;
                float rg = sigf(acc[(mf * 6 + 0 + uh) * 4 + e]);
                float zg = sigf(acc[(mf * 6 + 2 + uh) * 4 + e]);
                float nn = tanh_hw(accN[(mf * 2 + uh) * 4 + e] + rg * acc[(mf * 6 + 4 + uh) * 4 + e]);
                float ho = (q == 0) ? holdf.x : holdf.y;
                hn[q] = (1.0f - zg) * nn + zg * ho;
            }
            AnxtW[widx] = packh2(hn[0], hn[1]);
        }
    };
    // ELU + store decode layer1 result (this warp: 8 cols x its M-half)
    auto elu_store = [&](const float* dacc) {
        #pragma unroll
        for (int mf = 0; mf < 2; mf++)
        #pragma unroll
        for (int h = 0; h < 2; h++) {
            int row = mh * 32 + mf * 16 + g8 + h * 8;
            int col = wsub * 8 + tig * 2;
            float v0 = dacc[mf * 4 + 2 * h]     + sbd1[col];
            float v1 = dacc[mf * 4 + 2 * h + 1] + sbd1[col + 1];
            v0 = v0 > 0.0f ? v0 : (__expf(v0) - 1.0f);
            v1 = v1 > 0.0f ? v1 : (__expf(v1) - 1.0f);
            *(unsigned*)(sDech + row * DECLD + col) = packh2(v0, v1);
        }
    };
    // full task (kb0..24), 16 cols at ub
    auto full_task = [&](int ub, const unsigned* Aw, unsigned* AnxtW) {
        float acc[48], accN[16];
        #pragma unroll
        for (int i = 0; i < 48; i++) acc[i] = 0.0f;
        #pragma unroll
        for (int i = 0; i < 16; i++) accN[i] = 0.0f;
        const uint2* Bbase = g_Bh + (size_t)(ub * 6) * 32 + lane;
        uint2 bb[2][6];
        #pragma unroll
        for (int f = 0; f < 6; f++) bb[0][f] = Bbase[f * 32];
        uint2 bni0 = g_Bnih[(ub * 2 + 0) * 32 + lane];
        uint2 bni1 = g_Bnih[(ub * 2 + 1) * 32 + lane];
        #pragma unroll
        for (int kb = 0; kb < NKB; kb++) {
            int cur = kb & 1;
            if (kb < NKB - 1) {
                const uint2* Bn = Bbase + (size_t)(kb + 1) * (NMAIN * 32);
                #pragma unroll
                for (int f = 0; f < 6; f++) bb[cur ^ 1][f] = Bn[f * 32];
            }
            unsigned a[8];
            load_afrag(a, Aw, kb);
            if (kb == 0) {
                #pragma unroll
                for (int mf = 0; mf < 2; mf++) {
                    mma_f16(&accN[(mf * 2 + 0) * 4], &a[mf * 4], bni0.x, bni0.y);
                    mma_f16(&accN[(mf * 2 + 1) * 4], &a[mf * 4], bni1.x, bni1.y);
                }
            }
            #pragma unroll
            for (int f = 0; f < 6; f++)
                #pragma unroll
                for (int mf = 0; mf < 2; mf++)
                    mma_f16(&acc[(mf * 6 + f) * 4], &a[mf * 4], bb[cur][f].x, bb[cur][f].y);
        }
        gru_epilogue(ub, acc, accN, Aw, AnxtW);
    };
    // phase3: decode layer2, state update, output, rowvec write (tid<64)
    auto phase3 = [&](int tcur, unsigned* AcurW, float pl0, float pl1, float pl2, bool rowvec) {
        const __half2* dp = (const __half2*)(sDech + tid * DECLD);
        float a0 = sbd2[0], a1 = sbd2[1], a2 = sbd2[2];
        #pragma unroll 8
        for (int k2 = 0; k2 < 32; k2++) {
            float2 f = __half22float2(dp[k2]);
            a0 += f.x * sWd2[2 * k2]       + f.y * sWd2[2 * k2 + 1];
            a1 += f.x * sWd2[64 + 2 * k2]  + f.y * sWd2[64 + 2 * k2 + 1];
            a2 += f.x * sWd2[128 + 2 * k2] + f.y * sWd2[128 + 2 * k2 + 1];
        }
        st0 += a0; st1 += a1; st2 += a2;
        float* op = out + ((size_t)(row0 + tid) * TSTEPS + (tcur - 1)) * 3;
        op[0] = st0; op[1] = st1; op[2] = st2;
        if (rowvec) {
            AcurW[tid * WLDH + 1] = packh2(st0, st1);
            AcurW[tid * WLDH + 2] = packh2(st2, gx * pl0);
            AcurW[tid * WLDH + 3] = packh2(gx * pl1, gx * pl2);
        }
    };

    for (int t = 0; t < TSTEPS; t++) {
        __half* Acur = (t & 1) ? sA1h : sA0h;
        __half* Anxt = (t & 1) ? sA0h : sA1h;
        const unsigned* Aw = (const unsigned*)Acur;
        unsigned* AcurW = (unsigned*)Acur;
        unsigned* AnxtW = (unsigned*)Anxt;

        if (t == 0) {
            #pragma unroll
            for (int task = 0; task < 3; task++)
                full_task(wsub + 8 * task, Aw, AnxtW);
        } else {
            // prefetch plan(t) for rowvec
            float pl0 = 0.0f, pl1 = 0.0f, pl2 = 0.0f;
            if (tid < 64) {
                const float* pp = plan + ((size_t)(row0 + tid) * TSTEPS + t) * 3;
                pl0 = pp[0]; pl1 = pp[1]; pl2 = pp[2];
            }
            // ---- merged task0: main kb1..24 + decode(hidden t) ----
            const int ub = wsub;
            float acc[48], dacc[8];
            #pragma unroll
            for (int i = 0; i < 48; i++) acc[i] = 0.0f;
            #pragma unroll
            for (int i = 0; i < 8; i++) dacc[i] = 0.0f;
            const uint2* Bbase = g_Bh + (size_t)(ub * 6) * 32 + lane;
            uint2 bb[2][6];
            #pragma unroll
            for (int f = 0; f < 6; f++)
                bb[1][f] = Bbase[(size_t)(NMAIN * 32) + f * 32];        // kb=1
            uint2 bd = g_Wd1h[wsub * 32 + lane];                        // kd=0
            #pragma unroll
            for (int kb = 1; kb <= 24; kb++) {
                int cur = kb & 1;
                if (kb < 24) {
                    const uint2* Bn = Bbase + (size_t)(kb + 1) * (NMAIN * 32);
                    #pragma unroll
                    for (int f = 0; f < 6; f++) bb[cur ^ 1][f] = Bn[f * 32];
                }
                uint2 bdc = bd;
                if (kb < 24) bd = g_Wd1h[(kb * 8 + wsub) * 32 + lane];
                unsigned a[8];
                load_afrag(a, Aw, kb);
                #pragma unroll
                for (int mf = 0; mf < 2; mf++)
                    mma_f16(&dacc[mf * 4], &a[mf * 4], bdc.x, bdc.y);
                #pragma unroll
                for (int f = 0; f < 6; f++)
                    #pragma unroll
                    for (int mf = 0; mf < 2; mf++)
                        mma_f16(&acc[(mf * 6 + f) * 4], &a[mf * 4], bb[cur][f].x, bb[cur][f].y);
            }
            // prefetch kb0's B + n_i B across the barriers
            uint2 b0f[6];
            #pragma unroll
            for (int f = 0; f < 6; f++) b0f[f] = Bbase[f * 32];
            uint2 bni0 = g_Bnih[(ub * 2 + 0) * 32 + lane];
            uint2 bni1 = g_Bnih[(ub * 2 + 1) * 32 + lane];

            elu_store(dacc);
            __syncthreads();
            if (tid < 64) phase3(t, AcurW, pl0, pl1, pl2, true);
            __syncthreads();

            // kb0 (rowvec) + n_i + epilogue for task0
            {
                float accN[16];
                #pragma unroll
                for (int i = 0; i < 16; i++) accN[i] = 0.0f;
                unsigned a[8];
                load_afrag(a, Aw, 0);
                #pragma unroll
                for (int mf = 0; mf < 2; mf++) {
                    mma_f16(&accN[(mf * 2 + 0) * 4], &a[mf * 4], bni0.x, bni0.y);
                    mma_f16(&accN[(mf * 2 + 1) * 4], &a[mf * 4], bni1.x, bni1.y);
                }
                #pragma unroll
                for (int f = 0; f < 6; f++)
                    #pragma unroll
                    for (int mf = 0; mf < 2; mf++)
                        mma_f16(&acc[(mf * 6 + f) * 4], &a[mf * 4], b0f[f].x, b0f[f].y);
                gru_epilogue(ub, acc, accN, Aw, AnxtW);
            }
            // tasks 1..2 full
            full_task(wsub + 8, Aw, AnxtW);
            full_task(wsub + 16, Aw, AnxtW);
        }
        __syncthreads();
    }

    // ---- final decode of hidden(TSTEPS) -> out[TSTEPS-1] ----
    {
        const __half* Af = (TSTEPS & 1) ? sA1h : sA0h;
        const unsigned* Aw = (const unsigned*)Af;
        float dacc[8];
        #pragma unroll
        for (int i = 0; i < 8; i++) dacc[i] = 0.0f;
        uint2 bd = g_Wd1h[wsub * 32 + lane];
        #pragma unroll
        for (int kb = 1; kb <= 24; kb++) {
            uint2 bdc = bd;
            if (kb < 24) bd = g_Wd1h[(kb * 8 + wsub) * 32 + lane];
            unsigned a[8];
            load_afrag(a, Aw, kb);
            #pragma unroll
            for (int mf = 0; mf < 2; mf++)
                mma_f16(&dacc[mf * 4], &a[mf * 4], bdc.x, bdc.y);
        }
        elu_store(dacc);
        __syncthreads();
        if (tid < 64) phase3(TSTEPS, (unsigned*)Af, 0.0f, 0.0f, 0.0f, false);
    }
}

// -------- launch --------
extern "C" void kernel_launch(void* const* d_in, const int* in_sizes, int n_in,
                              void* d_out, int out_size) {
    const float* init_hidden = (const float*)d_in[0];
    const float* plan        = (const float*)d_in[1];
    const float* gatep       = (const float*)d_in[2];
    const float* init_state  = (const float*)d_in[3];
    const float* Wp   = (const float*)d_in[4];
    const float* bp   = (const float*)d_in[5];
    const float* Ws   = (const float*)d_in[6];
    const float* bs   = (const float*)d_in[7];
    const float* W_ih = (const float*)d_in[8];
    const float* b_ih = (const float*)d_in[9];
    const float* W_hh = (const float*)d_in[10];
    const float* b_hh = (const float*)d_in[11];
    const float* Wd1  = (const float*)d_in[12];
    const float* bd1  = (const float*)d_in[13];
    const float* Wd2  = (const float*)d_in[14];
    const float* bd2  = (const float*)d_in[15];
    float* out = (float*)d_out;

    prep_kernel<<<480, 256>>>(W_ih, b_ih, W_hh, b_hh, Wp, bp, Ws, bs, Wd1);

    const size_t smem_bytes = (size_t)(2 * AHSZ + 64 * DECLD) * sizeof(__half)
                            + (64 + 192 + 4) * sizeof(float);
    cudaFuncSetAttribute(gru_kernel, cudaFuncAttributeMaxDynamicSharedMemorySize,
                         (int)smem_bytes);

    gru_kernel<<<BATCH / MROWS, NTH, smem_bytes>>>(
        init_hidden, plan, gatep, init_state, bd1, Wd2, bd2, out);
}

// round 17
// speedup vs baseline: 1.0451x; 1.0451x over previous
#include <cuda_runtime.h>
#include <cuda_fp16.h>
#include <cstdint>

// Problem constants
#define BATCH   32768
#define TSTEPS  30
#define HID     384
// K layout: cols 0..7 rowvec, 8..15 zero, 16..399 hidden  (kb0 = pure rowvec block)
#define NKB     25      // K blocks of 16
#define NMAIN   144     // fragments per kb (24 ub * 6: gate3 x uh2)
#define MROWS   64      // batch rows per CTA
#define NTH     256     // 8 warps; 2 CTAs/SM
#define LDHH    408     // sA row stride in halfs
#define WLDH    204     // row stride in 32-bit words
#define AHSZ    (MROWS*LDHH)
#define DECLD   66      // sDec row stride in halfs

// -------- static device scratch (fp16 fragment tables) --------
__device__ uint2 g_Bh[NKB * NMAIN * 32];    // main GEMM B (r,z,n_h)
__device__ uint2 g_Bnih[48 * 32];           // n_i B: kb=0 only, 48 usb
__device__ uint2 g_Wd1h[24 * 8 * 32];       // decode B (kd = main kb-1)

__device__ __forceinline__ unsigned packh2(float a, float b) {
    __half2 h = __floats2half2_rn(a, b);
    return *reinterpret_cast<unsigned*>(&h);
}
__device__ __forceinline__ float tanh_hw(float x) {
    float y; asm("tanh.approx.f32 %0, %1;" : "=f"(y) : "f"(x)); return y;
}
__device__ __forceinline__ float sigf(float x) {
    return fmaf(0.5f, tanh_hw(0.5f * x), 0.5f);
}

__device__ __forceinline__ void mma_f16(float* c, const unsigned* a, unsigned b0, unsigned b1) {
    asm volatile(
        "mma.sync.aligned.m16n8k16.row.col.f32.f16.f16.f32 "
        "{%0,%1,%2,%3}, {%4,%5,%6,%7}, {%8,%9}, {%0,%1,%2,%3};\n"
        : "+f"(c[0]), "+f"(c[1]), "+f"(c[2]), "+f"(c[3])
        : "r"(a[0]), "r"(a[1]), "r"(a[2]), "r"(a[3]), "r"(b0), "r"(b1));
}

// -------- prep value helpers (identical to round 14) --------
__device__ float bval_main(int k, int ub, int colub,
                           const float* Wih, const float* bih,
                           const float* Whh, const float* bhh,
                           const float* Wp, const float* bp,
                           const float* Ws, const float* bs) {
    int gate = colub >> 4;                   // 0=r,1=z,2=n_h
    int u = ub * 16 + (colub & 15);
    if (k >= 16) {
        int grow = (gate == 2 ? 768 : gate * 384) + u;
        return Whh[grow * HID + (k - 16)];
    }
    if (gate == 2) return (k == 0) ? bhh[768 + u] : 0.0f;   // n_h: bias only
    if (k >= 8) return 0.0f;
    int grow = gate * 384 + u;
    const float* wr = Wih + grow * 128;
    float s = 0.0f;
    if (k == 0) {
        s = bih[grow] + bhh[grow];
        for (int m = 0; m < 128; m++) s += bs[m] * wr[m];
    } else if (k == 1) {
        for (int m = 0; m < 128; m++) s += bp[m] * wr[m];
    } else if (k < 5) {
        int d = k - 2;
        for (int m = 0; m < 128; m++) s += Ws[m * 3 + d] * wr[m];
    } else {
        int d = k - 5;
        for (int m = 0; m < 128; m++) s += Wp[m * 3 + d] * wr[m];
    }
    return s;
}

__device__ float bval_ni(int k, int u,
                         const float* Wih, const float* bih,
                         const float* Wp, const float* bp,
                         const float* Ws, const float* bs) {
    if (k >= 8) return 0.0f;                 // n_i: rowvec only
    int grow = 768 + u;
    const float* wr = Wih + grow * 128;
    float s = 0.0f;
    if (k == 0) {
        s = bih[grow];
        for (int m = 0; m < 128; m++) s += bs[m] * wr[m];
    } else if (k == 1) {
        for (int m = 0; m < 128; m++) s += bp[m] * wr[m];
    } else if (k < 5) {
        int d = k - 2;
        for (int m = 0; m < 128; m++) s += Ws[m * 3 + d] * wr[m];
    } else {
        int d = k - 5;
        for (int m = 0; m < 128; m++) s += Wp[m * 3 + d] * wr[m];
    }
    return s;
}

__global__ void prep_kernel(const float* __restrict__ W_ih, const float* __restrict__ b_ih,
                            const float* __restrict__ W_hh, const float* __restrict__ b_hh,
                            const float* __restrict__ Wp,  const float* __restrict__ bp,
                            const float* __restrict__ Ws,  const float* __restrict__ bs,
                            const float* __restrict__ Wd1) {
    int gid = blockIdx.x * blockDim.x + threadIdx.x;
    const int nMain = NKB * NMAIN;
    const int total = (nMain + 48 + 24 * 8) * 32;
    for (int w = gid; w < total; w += gridDim.x * blockDim.x) {
        int fid = w >> 5, lane = w & 31;
        int tig = lane & 3, g = lane >> 2;
        if (fid < nMain) {
            int kb = fid / NMAIN, rem = fid - kb * NMAIN;
            int ub = rem / 6, n8l = rem - ub * 6;
            int colub = n8l * 8 + g;
            int k0 = kb * 16;
            float v00 = bval_main(k0 + 2 * tig,     ub, colub, W_ih, b_ih, W_hh, b_hh, Wp, bp, Ws, bs);
            float v01 = bval_main(k0 + 2 * tig + 1, ub, colub, W_ih, b_ih, W_hh, b_hh, Wp, bp, Ws, bs);
            float v10 = bval_main(k0 + 2 * tig + 8, ub, colub, W_ih, b_ih, W_hh, b_hh, Wp, bp, Ws, bs);
            float v11 = bval_main(k0 + 2 * tig + 9, ub, colub, W_ih, b_ih, W_hh, b_hh, Wp, bp, Ws, bs);
            g_Bh[fid * 32 + lane] = make_uint2(packh2(v00, v01), packh2(v10, v11));
        } else if (fid < nMain + 48) {
            int usb = fid - nMain;
            int u = usb * 8 + g;
            float v00 = bval_ni(2 * tig,     u, W_ih, b_ih, Wp, bp, Ws, bs);
            float v01 = bval_ni(2 * tig + 1, u, W_ih, b_ih, Wp, bp, Ws, bs);
            g_Bnih[usb * 32 + lane] = make_uint2(packh2(v00, v01), packh2(0.0f, 0.0f));
        } else {
            int f = fid - nMain - 48;        // 24 kd * 8 c8 ; kd = main kb-1
            int kd = f >> 3, c8 = f & 7;
            int n = c8 * 8 + g;
            int k = kd * 16 + 2 * tig;
            float v00 = Wd1[n * HID + k];
            float v01 = Wd1[n * HID + k + 1];
            float v10 = Wd1[n * HID + k + 8];
            float v11 = Wd1[n * HID + k + 9];
            g_Wd1h[f * 32 + lane] = make_uint2(packh2(v00, v01), packh2(v10, v11));
        }
    }
}

// -------- main fused GRU rollout: fp16 MMA, fused decode, 2 CTAs/SM --------
__global__ __launch_bounds__(NTH, 2)
void gru_kernel(const float* __restrict__ init_hidden,
                const float* __restrict__ plan,
                const float* __restrict__ gate,
                const float* __restrict__ init_state,
                const float* __restrict__ bd1,
                const float* __restrict__ Wd2,
                const float* __restrict__ bd2,
                float* __restrict__ out) {
    extern __shared__ char smraw[];
    __half* sA0h  = (__half*)smraw;                 // [64][408] ping
    __half* sA1h  = sA0h + AHSZ;                    // pong
    __half* sDech = sA1h + AHSZ;                    // [64][66]
    float*  sbd1  = (float*)(sDech + 64 * DECLD);   // [64]
    float*  sWd2  = sbd1 + 64;                      // [192]
    float*  sbd2  = sWd2 + 192;                     // [4]

    const int tid  = threadIdx.x;
    const int warp = tid >> 5;
    const int lane = tid & 31;
    const int g8   = lane >> 2;
    const int tig  = lane & 3;
    const int row0 = blockIdx.x * MROWS;

    float st0 = 0.0f, st1 = 0.0f, st2 = 0.0f, gx = 0.0f;   // state lanes (tid<64)

    // ---- init ----
    for (int i = tid; i < MROWS * HID; i += NTH) {
        int r = i / HID, u = i - r * HID;
        sA0h[r * LDHH + 16 + u] = __float2half_rn(init_hidden[(size_t)row0 * HID + i]);
    }
    for (int i = tid; i < MROWS * 8; i += NTH) {   // zero cols 8..15, both buffers
        int r = i >> 3, c = i & 7;
        sA0h[r * LDHH + 8 + c] = __ushort_as_half(0);
        sA1h[r * LDHH + 8 + c] = __ushort_as_half(0);
    }
    if (tid < 64) {
        gx  = gate[row0 + tid];
        st0 = init_state[(size_t)(row0 + tid) * 3 + 0];
        st1 = init_state[(size_t)(row0 + tid) * 3 + 1];
        st2 = init_state[(size_t)(row0 + tid) * 3 + 2];
        const float* pp = plan + (size_t)(row0 + tid) * TSTEPS * 3;   // t=0
        unsigned w0 = packh2(1.0f, gx);
        ((unsigned*)sA0h)[tid * WLDH + 0] = w0;
        ((unsigned*)sA1h)[tid * WLDH + 0] = w0;
        ((unsigned*)sA0h)[tid * WLDH + 1] = packh2(st0, st1);
        ((unsigned*)sA0h)[tid * WLDH + 2] = packh2(st2, gx * pp[0]);
        ((unsigned*)sA0h)[tid * WLDH + 3] = packh2(gx * pp[1], gx * pp[2]);
        sbd1[tid] = bd1[tid];
    }
    if (tid < 192) sWd2[tid] = Wd2[tid];
    if (tid < 3)   sbd2[tid] = bd2[tid];
    __syncthreads();

    // A-fragment loader (word wbase = kb*8+tig -> cols 16kb+2tig..)
    auto load_afrag = [&](unsigned* a, const unsigned* Aw, int kb) {
        #pragma unroll
        for (int mf = 0; mf < 4; mf++) {
            int r0 = mf * 16 + g8;
            int wb = kb * 8 + tig;
            a[mf * 4 + 0] = Aw[r0 * WLDH + wb];
            a[mf * 4 + 1] = Aw[(r0 + 8) * WLDH + wb];
            a[mf * 4 + 2] = Aw[r0 * WLDH + wb + 4];
            a[mf * 4 + 3] = Aw[(r0 + 8) * WLDH + wb + 4];
        }
    };
    // GRU epilogue for one usb (acc complete)
    auto gru_epilogue = [&](int usb, const float* acc, const float* accN,
                            const unsigned* Aw, unsigned* AnxtW) {
        #pragma unroll
        for (int mf = 0; mf < 4; mf++)
        #pragma unroll
        for (int h = 0; h < 2; h++) {
            int row = mf * 16 + g8 + h * 8;
            int widx = row * WLDH + 8 + usb * 4 + tig;
            __half2 hold2 = *(const __half2*)&Aw[widx];
            float2 holdf = __half22float2(hold2);
            float hn[2];
            #pragma unroll
            for (int q = 0; q < 2; q++) {
                int e = 2 * h + q;
                float rg = sigf(acc[(mf * 3 + 0) * 4 + e]);
                float zg = sigf(acc[(mf * 3 + 1) * 4 + e]);
                float nn = tanh_hw(accN[mf * 4 + e] + rg * acc[(mf * 3 + 2) * 4 + e]);
                float ho = (q == 0) ? holdf.x : holdf.y;
                hn[q] = (1.0f - zg) * nn + zg * ho;
            }
            AnxtW[widx] = packh2(hn[0], hn[1]);
        }
    };
    // ELU + store decode layer1 result
    auto elu_store = [&](const float* dacc) {
        #pragma unroll
        for (int mf = 0; mf < 4; mf++)
        #pragma unroll
        for (int h = 0; h < 2; h++) {
            int row = mf * 16 + g8 + h * 8;
            int col = warp * 8 + tig * 2;
            float v0 = dacc[mf * 4 + 2 * h]     + sbd1[col];
            float v1 = dacc[mf * 4 + 2 * h + 1] + sbd1[col + 1];
            v0 = v0 > 0.0f ? v0 : (__expf(v0) - 1.0f);
            v1 = v1 > 0.0f ? v1 : (__expf(v1) - 1.0f);
            *(unsigned*)(sDech + row * DECLD + col) = packh2(v0, v1);
        }
    };
    // full task: kb1..24 mainloop (3-slot, distance-2 B pipe), then kb0 + n_i last
    auto full_task = [&](int usb, const unsigned* Aw, unsigned* AnxtW) {
        int ub = usb >> 1, uh = usb & 1;
        float acc[48];
        #pragma unroll
        for (int i = 0; i < 48; i++) acc[i] = 0.0f;
        const uint2* Bbase = g_Bh + (size_t)(ub * 6 + uh) * 32 + lane;
        uint2 bb[3][3];
        #pragma unroll
        for (int s = 0; s < 2; s++)
            #pragma unroll
            for (int gi = 0; gi < 3; gi++)
                bb[s][gi] = Bbase[(size_t)(s + 1) * (NMAIN * 32) + gi * 64];
        uint2 b0f[3];
        #pragma unroll
        for (int gi = 0; gi < 3; gi++) b0f[gi] = Bbase[gi * 64];
        uint2 bni = g_Bnih[usb * 32 + lane];
        #pragma unroll
        for (int kb = 1; kb <= 24; kb++) {
            int cur = (kb - 1) % 3;
            if (kb + 2 <= 24) {
                const uint2* Bn = Bbase + (size_t)(kb + 2) * (NMAIN * 32);
                #pragma unroll
                for (int gi = 0; gi < 3; gi++) bb[(kb + 1) % 3][gi] = Bn[gi * 64];
            }
            unsigned a[16];
            load_afrag(a, Aw, kb);
            #pragma unroll
            for (int gi = 0; gi < 3; gi++)
                #pragma unroll
                for (int mf = 0; mf < 4; mf++)
                    mma_f16(&acc[(mf * 3 + gi) * 4], &a[mf * 4], bb[cur][gi].x, bb[cur][gi].y);
        }
        // kb0 (rowvec) + n_i last
        float accN[16];
        #pragma unroll
        for (int i = 0; i < 16; i++) accN[i] = 0.0f;
        unsigned a[16];
        load_afrag(a, Aw, 0);
        #pragma unroll
        for (int mf = 0; mf < 4; mf++)
            mma_f16(&accN[mf * 4], &a[mf * 4], bni.x, bni.y);
        #pragma unroll
        for (int gi = 0; gi < 3; gi++)
            #pragma unroll
            for (int mf = 0; mf < 4; mf++)
                mma_f16(&acc[(mf * 3 + gi) * 4], &a[mf * 4], b0f[gi].x, b0f[gi].y);
        gru_epilogue(usb, acc, accN, Aw, AnxtW);
    };
    // phase3: decode layer2, state update, output, rowvec write
    auto phase3 = [&](int tcur, unsigned* AcurW, float pl0, float pl1, float pl2, bool rowvec) {
        const __half2* dp = (const __half2*)(sDech + tid * DECLD);
        float a0 = sbd2[0], a1 = sbd2[1], a2 = sbd2[2];
        #pragma unroll 8
        for (int k2 = 0; k2 < 32; k2++) {
            float2 f = __half22float2(dp[k2]);
            a0 += f.x * sWd2[2 * k2]       + f.y * sWd2[2 * k2 + 1];
            a1 += f.x * sWd2[64 + 2 * k2]  + f.y * sWd2[64 + 2 * k2 + 1];
            a2 += f.x * sWd2[128 + 2 * k2] + f.y * sWd2[128 + 2 * k2 + 1];
        }
        st0 += a0; st1 += a1; st2 += a2;
        float* op = out + ((size_t)(row0 + tid) * TSTEPS + (tcur - 1)) * 3;
        op[0] = st0; op[1] = st1; op[2] = st2;
        if (rowvec) {
            AcurW[tid * WLDH + 1] = packh2(st0, st1);
            AcurW[tid * WLDH + 2] = packh2(st2, gx * pl0);
            AcurW[tid * WLDH + 3] = packh2(gx * pl1, gx * pl2);
        }
    };

    for (int t = 0; t < TSTEPS; t++) {
        __half* Acur = (t & 1) ? sA1h : sA0h;
        __half* Anxt = (t & 1) ? sA0h : sA1h;
        const unsigned* Aw = (const unsigned*)Acur;
        unsigned* AcurW = (unsigned*)Acur;
        unsigned* AnxtW = (unsigned*)Anxt;

        if (t == 0) {
            for (int task = 0; task < 6; task++)
                full_task(warp + 8 * task, Aw, AnxtW);
        } else {
            // prefetch plan(t) for rowvec
            float pl0 = 0.0f, pl1 = 0.0f, pl2 = 0.0f;
            if (tid < 64) {
                const float* pp = plan + ((size_t)(row0 + tid) * TSTEPS + t) * 3;
                pl0 = pp[0]; pl1 = pp[1]; pl2 = pp[2];
            }
            // ---- merged task0: main kb1..24 + decode(hidden t), 3-slot dist-2 pipe ----
            const int usb = warp;
            const int ub = usb >> 1, uh = usb & 1;
            float acc[48], dacc[16];
            #pragma unroll
            for (int i = 0; i < 48; i++) acc[i] = 0.0f;
            #pragma unroll
            for (int i = 0; i < 16; i++) dacc[i] = 0.0f;
            const uint2* Bbase = g_Bh + (size_t)(ub * 6 + uh) * 32 + lane;
            uint2 bb[3][3];
            #pragma unroll
            for (int s = 0; s < 2; s++)
                #pragma unroll
                for (int gi = 0; gi < 3; gi++)
                    bb[s][gi] = Bbase[(size_t)(s + 1) * (NMAIN * 32) + gi * 64];
            uint2 bd = g_Wd1h[warp * 32 + lane];                        // kd=0
            #pragma unroll
            for (int kb = 1; kb <= 24; kb++) {
                int cur = (kb - 1) % 3;
                if (kb + 2 <= 24) {
                    const uint2* Bn = Bbase + (size_t)(kb + 2) * (NMAIN * 32);
                    #pragma unroll
                    for (int gi = 0; gi < 3; gi++) bb[(kb + 1) % 3][gi] = Bn[gi * 64];
                }
                uint2 bdc = bd;
                if (kb < 24) bd = g_Wd1h[(kb * 8 + warp) * 32 + lane];
                unsigned a[16];
                load_afrag(a, Aw, kb);
                #pragma unroll
                for (int mf = 0; mf < 4; mf++)
                    mma_f16(&dacc[mf * 4], &a[mf * 4], bdc.x, bdc.y);
                #pragma unroll
                for (int gi = 0; gi < 3; gi++)
                    #pragma unroll
                    for (int mf = 0; mf < 4; mf++)
                        mma_f16(&acc[(mf * 3 + gi) * 4], &a[mf * 4], bb[cur][gi].x, bb[cur][gi].y);
            }
            // prefetch kb0's B + n_i B across the barriers
            uint2 b0f[3];
            #pragma unroll
            for (int gi = 0; gi < 3; gi++) b0f[gi] = Bbase[gi * 64];
            uint2 bni = g_Bnih[usb * 32 + lane];

            elu_store(dacc);
            __syncthreads();
            if (tid < 64) phase3(t, AcurW, pl0, pl1, pl2, true);
            __syncthreads();

            // kb0 (rowvec) + n_i + epilogue for task0
            {
                float accN[16];
                #pragma unroll
                for (int i = 0; i < 16; i++) accN[i] = 0.0f;
                unsigned a[16];
                load_afrag(a, Aw, 0);
                #pragma unroll
                for (int mf = 0; mf < 4; mf++)
                    mma_f16(&accN[mf * 4], &a[mf * 4], bni.x, bni.y);
                #pragma unroll
                for (int gi = 0; gi < 3; gi++)
                    #pragma unroll
                    for (int mf = 0; mf < 4; mf++)
                        mma_f16(&acc[(mf * 3 + gi) * 4], &a[mf * 4], b0f[gi].x, b0f[gi].y);
                gru_epilogue(usb, acc, accN, Aw, AnxtW);
            }
            // tasks 1..5 full
            for (int task = 1; task < 6; task++)
                full_task(warp + 8 * task, Aw, AnxtW);
        }
        __syncthreads();
    }

    // ---- final decode of hidden(TSTEPS) -> out[TSTEPS-1] ----
    {
        const __half* Af = (TSTEPS & 1) ? sA1h : sA0h;
        const unsigned* Aw = (const unsigned*)Af;
        float dacc[16];
        #pragma unroll
        for (int i = 0; i < 16; i++) dacc[i] = 0.0f;
        uint2 bd = g_Wd1h[warp * 32 + lane];
        #pragma unroll
        for (int kb = 1; kb <= 24; kb++) {
            uint2 bdc = bd;
            if (kb < 24) bd = g_Wd1h[(kb * 8 + warp) * 32 + lane];
            unsigned a[16];
            load_afrag(a, Aw, kb);
            #pragma unroll
            for (int mf = 0; mf < 4; mf++)
                mma_f16(&dacc[mf * 4], &a[mf * 4], bdc.x, bdc.y);
        }
        elu_store(dacc);
        __syncthreads();
        if (tid < 64) phase3(TSTEPS, (unsigned*)Af, 0.0f, 0.0f, 0.0f, false);
    }
}

// -------- launch --------
extern "C" void kernel_launch(void* const* d_in, const int* in_sizes, int n_in,
                              void* d_out, int out_size) {
    const float* init_hidden = (const float*)d_in[0];
    const float* plan        = (const float*)d_in[1];
    const float* gatep       = (const float*)d_in[2];
    const float* init_state  = (const float*)d_in[3];
    const float* Wp   = (const float*)d_in[4];
    const float* bp   = (const float*)d_in[5];
    const float* Ws   = (const float*)d_in[6];
    const float* bs   = (const float*)d_in[7];
    const float* W_ih = (const float*)d_in[8];
    const float* b_ih = (const float*)d_in[9];
    const float* W_hh = (const float*)d_in[10];
    const float* b_hh = (const float*)d_in[11];
    const float* Wd1  = (const float*)d_in[12];
    const float* bd1  = (const float*)d_in[13];
    const float* Wd2  = (const float*)d_in[14];
    const float* bd2  = (const float*)d_in[15];
    float* out = (float*)d_out;

    prep_kernel<<<480, 256>>>(W_ih, b_ih, W_hh, b_hh, Wp, bp, Ws, bs, Wd1);

    const size_t smem_bytes = (size_t)(2 * AHSZ + 64 * DECLD) * sizeof(__half)
                            + (64 + 192 + 4) * sizeof(float);
    cudaFuncSetAttribute(gru_kernel, cudaFuncAttributeMaxDynamicSharedMemorySize,
                         (int)smem_bytes);

    gru_kernel<<<BATCH / MROWS, NTH, smem_bytes>>>(
        init_hidden, plan, gatep, init_state, bd1, Wd2, bd2, out);
}